// round 13
// baseline (speedup 1.0000x reference)
#include <cuda_runtime.h>
#include <math.h>

#define IN_SIZE 448
#define OUT_SIZE 224
#define NBATCH 64
#define ROWS_PER_BLOCK 4
#define SROWS 10            // staged input rows per block (max span is 9)

// Scratch (allocation-free per harness rules): per-batch sigmoid-mask tables + crop boxes.
__device__ float g_mrow[NBATCH][IN_SIZE];
__device__ float g_mcol[NBATCH][IN_SIZE];
__device__ float4 g_box[NBATCH];   // (w_off, w_end, h_off, h_end)

__device__ __forceinline__ float sig10(float z) {
    return 1.0f / (1.0f + expf(-10.0f * z));
}

__global__ void racnn_prep_kernel(const float* __restrict__ locs) {
    int b = blockIdx.x;
    int t = threadIdx.x;  // 0..447

    float tx = locs[b * 3 + 0];
    float ty = locs[b * 3 + 1];
    float tl = locs[b * 3 + 2];

    tl = fmaxf(tl, (float)IN_SIZE / 3.0f);
    tx = fminf(fmaxf(tx, tl), (float)IN_SIZE - tl);
    ty = fminf(fmaxf(ty, tl), (float)IN_SIZE - tl);

    float w_off = fmaxf(floorf(tx - tl), 0.0f);
    float h_off = fmaxf(floorf(ty - tl), 0.0f);
    float w_end = fminf(floorf(tx + tl), (float)IN_SIZE);
    float h_end = fminf(floorf(ty + tl), (float)IN_SIZE);

    float fi = (float)t;
    g_mrow[b][t] = sig10(fi - w_off) - sig10(fi - w_end);
    g_mcol[b][t] = sig10(fi - h_off) - sig10(fi - h_end);

    if (t == 0) g_box[b] = make_float4(w_off, w_end, h_off, h_end);
}

// Block = 4 output rows x 224 cols x 3 channels.
// Stage SROWS full input rows per channel into smem with coalesced float4 loads
// (kills gather L1 wavefronts), then bilinear-interpolate out of smem.
__global__ __launch_bounds__(OUT_SIZE) void racnn_main_kernel(
    const float* __restrict__ img, float* __restrict__ out) {
    __shared__ float s_rows[SROWS][IN_SIZE];   // 17.9 KB

    int jc      = threadIdx.x;                  // 0..223
    int jr_base = blockIdx.x * ROWS_PER_BLOCK;  // 0,4,...,220
    int b       = blockIdx.y;                   // 0..63

    float4 box = g_box[b];
    float w_off = box.x, w_end = box.y, h_off = box.z, h_end = box.w;

    const float inv = 1.0f / (float)(OUT_SIZE - 1);
    float rscale = (w_end - w_off - 1.0f) * inv;
    float cscale = (h_end - h_off - 1.0f) * inv;

    // Column weights (per thread, shared across 12 outputs)
    float src_c = h_off + (float)jc * cscale;
    float c0f = fminf(fmaxf(floorf(src_c), 0.0f), (float)(IN_SIZE - 1));
    float wc = src_c - c0f;
    int c0 = (int)c0f;
    int c1 = min(c0 + 1, IN_SIZE - 1);
    float b0 = (1.0f - wc) * __ldg(&g_mcol[b][c0]);
    float b1 = wc          * __ldg(&g_mcol[b][c1]);

    // Row weights + local (staged) row indices for the block's 4 output rows
    float a0[ROWS_PER_BLOCK], a1[ROWS_PER_BLOCK];
    int   lr0[ROWS_PER_BLOCK], lr1[ROWS_PER_BLOCK];

    // r_lo = first staged row = r0 of the block's first output row
    float src_r0 = w_off + (float)jr_base * rscale;
    int r_lo = (int)fminf(fmaxf(floorf(src_r0), 0.0f), (float)(IN_SIZE - 1));

    #pragma unroll
    for (int rr = 0; rr < ROWS_PER_BLOCK; rr++) {
        float src_r = w_off + (float)(jr_base + rr) * rscale;
        float r0f = fminf(fmaxf(floorf(src_r), 0.0f), (float)(IN_SIZE - 1));
        float wr = src_r - r0f;
        int r0 = (int)r0f;
        int r1 = min(r0 + 1, IN_SIZE - 1);
        a0[rr] = (1.0f - wr) * __ldg(&g_mrow[b][r0]);
        a1[rr] = wr          * __ldg(&g_mrow[b][r1]);
        lr0[rr] = r0 - r_lo;   // in [0, SROWS)
        lr1[rr] = r1 - r_lo;
    }

    const float* base  = img + (size_t)b * 3 * IN_SIZE * IN_SIZE;
    float*       obase = out + (size_t)b * 3 * OUT_SIZE * OUT_SIZE
                             + (size_t)jr_base * OUT_SIZE + jc;

    // Staged-row global row indices (clamped); duplicates at image edge are harmless.
    #pragma unroll
    for (int ch = 0; ch < 3; ch++) {
        const float* p = base + (size_t)ch * IN_SIZE * IN_SIZE;

        __syncthreads();   // previous channel's smem reads complete
        // Stage SROWS x 448 floats = 1120 float4, 5 per thread, fully coalesced.
        #pragma unroll
        for (int i = 0; i < 5; i++) {
            int f4 = threadIdx.x + i * OUT_SIZE;          // 0..1119
            int row = f4 / (IN_SIZE / 4);                  // 0..9
            int col4 = f4 % (IN_SIZE / 4);
            int grow = min(r_lo + row, IN_SIZE - 1);
            float4 v = __ldg((const float4*)(p + (size_t)grow * IN_SIZE) + col4);
            *((float4*)&s_rows[row][col4 * 4]) = v;
        }
        __syncthreads();

        float* o = obase + (size_t)ch * OUT_SIZE * OUT_SIZE;
        #pragma unroll
        for (int rr = 0; rr < ROWS_PER_BLOCK; rr++) {
            float p00 = s_rows[lr0[rr]][c0];
            float p01 = s_rows[lr0[rr]][c1];
            float p10 = s_rows[lr1[rr]][c0];
            float p11 = s_rows[lr1[rr]][c1];
            o[(size_t)rr * OUT_SIZE] =
                a0[rr] * (b0 * p00 + b1 * p01) +
                a1[rr] * (b0 * p10 + b1 * p11);
        }
    }
}

extern "C" void kernel_launch(void* const* d_in, const int* in_sizes, int n_in,
                              void* d_out, int out_size) {
    const float* images = (const float*)d_in[0];  // [64, 3, 448, 448] f32
    const float* locs   = (const float*)d_in[1];  // [64, 3] f32
    float* out = (float*)d_out;                   // [64, 3, 224, 224] f32

    racnn_prep_kernel<<<NBATCH, IN_SIZE>>>(locs);

    dim3 grid(OUT_SIZE / ROWS_PER_BLOCK, NBATCH);   // (56, 64)
    racnn_main_kernel<<<grid, OUT_SIZE>>>(images, out);
}